// round 1
// baseline (speedup 1.0000x reference)
#include <cuda_runtime.h>
#include <cstdint>

// StableZeroDiv: out = x * (1/y if y != 0 else 0)  == (y != 0) ? x / y : 0
// B=64, N=1048576 -> 67,108,864 fp32 elements. Pure HBM-bound elementwise.
// Strategy: float4 vectorized, exact grid, one pass.

__global__ void __launch_bounds__(256)
stable_zero_div_vec4(const float4* __restrict__ x,
                     const float4* __restrict__ y,
                     float4* __restrict__ out,
                     int n_vec)
{
    int i = blockIdx.x * blockDim.x + threadIdx.x;
    if (i >= n_vec) return;

    float4 xv = x[i];
    float4 yv = y[i];
    float4 ov;
    ov.x = (yv.x != 0.0f) ? (xv.x / yv.x) : 0.0f;
    ov.y = (yv.y != 0.0f) ? (xv.y / yv.y) : 0.0f;
    ov.z = (yv.z != 0.0f) ? (xv.z / yv.z) : 0.0f;
    ov.w = (yv.w != 0.0f) ? (xv.w / yv.w) : 0.0f;
    out[i] = ov;
}

// Scalar tail fallback (not expected to trigger: total elems divisible by 4).
__global__ void stable_zero_div_tail(const float* __restrict__ x,
                                     const float* __restrict__ y,
                                     float* __restrict__ out,
                                     int start, int n)
{
    int i = start + blockIdx.x * blockDim.x + threadIdx.x;
    if (i >= n) return;
    float yv = y[i];
    out[i] = (yv != 0.0f) ? (x[i] / yv) : 0.0f;
}

extern "C" void kernel_launch(void* const* d_in, const int* in_sizes, int n_in,
                              void* d_out, int out_size)
{
    const float* x = (const float*)d_in[0];
    const float* y = (const float*)d_in[1];
    float* out = (float*)d_out;

    int n = in_sizes[0];          // total elements (B*N)
    int n_vec = n >> 2;           // float4 count

    if (n_vec > 0) {
        const int threads = 256;
        int blocks = (n_vec + threads - 1) / threads;
        stable_zero_div_vec4<<<blocks, threads>>>(
            (const float4*)x, (const float4*)y, (float4*)out, n_vec);
    }

    int tail_start = n_vec << 2;
    int tail = n - tail_start;
    if (tail > 0) {
        stable_zero_div_tail<<<1, 256>>>(x, y, out, tail_start, n);
    }
}

// round 4
// speedup vs baseline: 1.0717x; 1.0717x over previous
#include <cuda_runtime.h>
#include <cstdint>

// StableZeroDiv: out = (y != 0) ? x / y : 0
// 67,108,864 fp32 elements, pure HBM-bound.
// R2: approx divide (MUFU.RCP+FMUL), streaming ld/st hints, 2x float4/thread.

__device__ __forceinline__ float4 szd(float4 xv, float4 yv)
{
    float4 ov;
    ov.x = (yv.x != 0.0f) ? __fdividef(xv.x, yv.x) : 0.0f;
    ov.y = (yv.y != 0.0f) ? __fdividef(xv.y, yv.y) : 0.0f;
    ov.z = (yv.z != 0.0f) ? __fdividef(xv.z, yv.z) : 0.0f;
    ov.w = (yv.w != 0.0f) ? __fdividef(xv.w, yv.w) : 0.0f;
    return ov;
}

// Each block handles 2*256 contiguous float4s; thread t does t and t+256.
__global__ void __launch_bounds__(256)
stable_zero_div_vec4x2(const float4* __restrict__ x,
                       const float4* __restrict__ y,
                       float4* __restrict__ out,
                       int n_vec)
{
    int base = blockIdx.x * 512 + threadIdx.x;
    int i0 = base;
    int i1 = base + 256;

    if (i1 < n_vec) {
        // Batch all 4 loads up front for MLP.
        float4 x0 = __ldcs(&x[i0]);
        float4 y0 = __ldcs(&y[i0]);
        float4 x1 = __ldcs(&x[i1]);
        float4 y1 = __ldcs(&y[i1]);
        __stcs(&out[i0], szd(x0, y0));
        __stcs(&out[i1], szd(x1, y1));
    } else {
        if (i0 < n_vec) {
            float4 x0 = __ldcs(&x[i0]);
            float4 y0 = __ldcs(&y[i0]);
            __stcs(&out[i0], szd(x0, y0));
        }
    }
}

// Scalar tail fallback (not expected: total elems divisible by 4).
__global__ void stable_zero_div_tail(const float* __restrict__ x,
                                     const float* __restrict__ y,
                                     float* __restrict__ out,
                                     int start, int n)
{
    int i = start + blockIdx.x * blockDim.x + threadIdx.x;
    if (i >= n) return;
    float yv = y[i];
    out[i] = (yv != 0.0f) ? __fdividef(x[i], yv) : 0.0f;
}

extern "C" void kernel_launch(void* const* d_in, const int* in_sizes, int n_in,
                              void* d_out, int out_size)
{
    const float* x = (const float*)d_in[0];
    const float* y = (const float*)d_in[1];
    float* out = (float*)d_out;

    int n = in_sizes[0];          // total elements (B*N)
    int n_vec = n >> 2;           // float4 count

    if (n_vec > 0) {
        const int per_block = 512;  // float4s per block
        int blocks = (n_vec + per_block - 1) / per_block;
        stable_zero_div_vec4x2<<<blocks, 256>>>(
            (const float4*)x, (const float4*)y, (float4*)out, n_vec);
    }

    int tail_start = n_vec << 2;
    int tail = n - tail_start;
    if (tail > 0) {
        stable_zero_div_tail<<<1, 256>>>(x, y, out, tail_start, n);
    }
}